// round 5
// baseline (speedup 1.0000x reference)
#include <cuda_runtime.h>
#include <math.h>
#include <float.h>
#include <stdint.h>

// Problem constants (fixed by the reference)
#define B_IMG  32
#define D_DIM  256
#define HW_SZ  4096     // H*W = 64*64
#define K_CB   512
#define NCLS   10
#define NSHR   10

// Tiling
#define TP     256      // pixels per block
#define NWARP  10       // warps per block
#define NTHR   (NWARP * 32)
#define KPG    6        // codes per warp-group
#define KT     (NWARP * KPG)   // 60 padded candidate codes
#define CBS2   258      // smem codebook row stride (EVEN: enables LDS.64 pairs)
#define CHROWS 16       // d-rows staged per chunk (double-buffered)
#define NCHNK  (D_DIM / CHROWS)

#define F32_INF __int_as_float(0x7f800000)

struct ClassRanges { int lo[NCLS]; int cnt[NCLS]; };

typedef unsigned long long ull;

// ---- packed f32x2 helpers (Blackwell): exact per-lane IEEE fp32 semantics --
__device__ __forceinline__ ull pack2(float x) {
    unsigned int b = __float_as_uint(x);
    ull r;
    asm("mov.b64 %0, {%1, %1};" : "=l"(r) : "r"(b));
    return r;
}
__device__ __forceinline__ void fma2(ull& d, ull a, ull b) {
    asm("fma.rn.f32x2 %0, %1, %2, %0;" : "+l"(d) : "l"(a), "l"(b));
}
__device__ __forceinline__ float2 unpack2(ull v) {
    unsigned int lo, hi;
    asm("mov.b64 {%0, %1}, %2;" : "=r"(lo), "=r"(hi) : "l"(v));
    return make_float2(__uint_as_float(lo), __uint_as_float(hi));
}

// ---- cp.async helpers ------------------------------------------------------
__device__ __forceinline__ unsigned int smem_u32(const void* p) {
    return (unsigned int)__cvta_generic_to_shared(p);
}
__device__ __forceinline__ void cp16(unsigned int dst, const void* src) {
    asm volatile("cp.async.cg.shared.global [%0], [%1], 16;"
                 :: "r"(dst), "l"(src) : "memory");
}
#define CP_COMMIT()  asm volatile("cp.async.commit_group;" ::: "memory")
#define CP_WAIT(n)   asm volatile("cp.async.wait_group %0;" :: "n"(n) : "memory")

// ----------------------------------------------------------------------------
// One block: image b, 256 contiguous pixels. Candidate codes = contiguous
// codebook slice [lo, lo+cnt) for this image's class, resident in smem.
//
// Bit-exact replication of the reference fp32 arithmetic (validated round 2):
//   A   = in_sqr  : sequential ascending sum of fl(x_d*x_d)  (mul then add)
//   g_k = x . c_k : sequential ascending fused-FMA chain
//   p_k = ||c_k||^2 (order non-critical: err ~1e-11 vs ulp(256)=3e-5 grid)
//   d_k = fl( fl(A + p_k) - 2*g_k );  argmin, first-min tie-break.
// ----------------------------------------------------------------------------
__global__ void __launch_bounds__(NTHR, 2)
vq_kernel(const float* __restrict__ z, const float* __restrict__ cb,
          const int* __restrict__ labels, float* __restrict__ out,
          ClassRanges cr)
{
    extern __shared__ float smem[];
    float* cb_s = smem;                       // [KT][CBS2]
    float* p_s  = cb_s + KT * CBS2;           // [64]  cb_sqr (+inf pads)
    float* A_s  = p_s + 64;                   // [256] in_sqr per pixel
    float* xb0  = A_s + 256;                  // [CHROWS][256] buffer 0
    float* xb1  = xb0 + CHROWS * 256;         // [CHROWS][256] buffer 1

    const int tid = threadIdx.x;
    const int tx  = tid & 31;                 // pixel-group lane
    const int ty  = tid >> 5;                 // code group (0..NWARP-1)
    const int b   = blockIdx.y;
    const int hw0 = blockIdx.x * TP;

    const int label = labels[b];
    const int lo    = cr.lo[label];
    const int cnt   = cr.cnt[label];          // 50 or 51

    const float* xbase = z + (size_t)b * D_DIM * HW_SZ + hw0;

    // ---- prologue: async-prefetch chunk 0 ----
    {
        const unsigned int dst0 = smem_u32(xb0);
        #pragma unroll
        for (int g = 0; g < 4; ++g) {
            const int idx = g * NTHR + tid;   // float4 index within chunk
            if (idx < CHROWS * 64) {
                const int row = idx >> 6;
                const int c4  = (idx & 63) << 2;
                cp16(dst0 + (unsigned)((row << 8) + c4) * 4u,
                     xbase + (size_t)row * HW_SZ + c4);
            }
        }
        CP_COMMIT();
    }

    // ---- load codebook slice (padded rows = 0), float2-vectorized ----
    for (int i = tid; i < KT * (D_DIM / 2); i += NTHR) {
        const int kk = i >> 7;                // 128 float2 per row
        const int d2 = (i & 127) << 1;
        float2 v = make_float2(0.0f, 0.0f);
        if (kk < cnt) v = *(const float2*)(cb + (size_t)(lo + kk) * D_DIM + d2);
        *(float2*)&cb_s[kk * CBS2 + d2] = v;
    }
    __syncthreads();

    // ---- cb_sqr per row (conflict-free: addr = 2kk + tx mod 32) ----
    #pragma unroll
    for (int j = 0; j < KPG; ++j) {
        const int kk = ty * KPG + j;
        float s = 0.0f;
        #pragma unroll
        for (int d = tx; d < D_DIM; d += 32) {
            const float v = cb_s[kk * CBS2 + d];
            s = __fadd_rn(s, __fmul_rn(v, v));
        }
        #pragma unroll
        for (int o = 16; o > 0; o >>= 1)
            s = __fadd_rn(s, __shfl_xor_sync(0xffffffffu, s, o));
        if (tx == 0)
            p_s[kk] = (kk < cnt) ? s : F32_INF;
    }

    // ---- main pass over 16 chunks of 16 d-rows, double-buffered ----
    // Thread (tx,ty) owns pixels {4tx+0..3} and {128+4tx+0..3}.
    ull acc[KPG][4];
    #pragma unroll
    for (int j = 0; j < KPG; ++j)
        #pragma unroll
        for (int r = 0; r < 4; ++r) acc[j][r] = 0ULL;
    float Aacc = 0.0f;                        // in_sqr chain for pixel == tid

    for (int ch = 0; ch < NCHNK; ++ch) {
        float* cur = (ch & 1) ? xb1 : xb0;
        float* nxt = (ch & 1) ? xb0 : xb1;
        if (ch + 1 < NCHNK) {
            const float* xs = xbase + (size_t)(ch + 1) * CHROWS * HW_SZ;
            const unsigned int dstn = smem_u32(nxt);
            #pragma unroll
            for (int g = 0; g < 4; ++g) {
                const int idx = g * NTHR + tid;
                if (idx < CHROWS * 64) {
                    const int row = idx >> 6;
                    const int c4  = (idx & 63) << 2;
                    cp16(dstn + (unsigned)((row << 8) + c4) * 4u,
                         xs + (size_t)row * HW_SZ + c4);
                }
            }
            CP_COMMIT();
            CP_WAIT(1);                       // cur's group complete
        } else {
            CP_WAIT(0);
        }
        __syncthreads();                      // cur visible to all threads

        // in_sqr: thread owns pixel tid (first 256 threads), ascending d
        if (tid < 256) {
            #pragma unroll
            for (int dd = 0; dd < CHROWS; ++dd) {
                const float v = cur[(dd << 8) + tid];
                Aacc = __fadd_rn(Aacc, __fmul_rn(v, v));
            }
        }

        // GEMM: 2 d per iteration; codes via LDS.64, x via LDS.128
        const int dc0 = ch * CHROWS;
        #pragma unroll 2
        for (int dd = 0; dd < CHROWS; dd += 2) {
            float2 cp[KPG];
            #pragma unroll
            for (int j = 0; j < KPG; ++j)
                cp[j] = *(const float2*)&cb_s[(ty * KPG + j) * CBS2 + dc0 + dd];

            ull xp[4];
            #pragma unroll
            for (int h = 0; h < 2; ++h) {     // the two d's
                const float* row = cur + ((dd + h) << 8);
                float4 a = *(const float4*)(row + (tx << 2));
                float4 c = *(const float4*)(row + 128 + (tx << 2));
                xp[0] = *(const ull*)&a.x;  xp[1] = *(const ull*)&a.z;
                xp[2] = *(const ull*)&c.x;  xp[3] = *(const ull*)&c.z;
                #pragma unroll
                for (int j = 0; j < KPG; ++j) {
                    const ull c2 = pack2(h ? cp[j].y : cp[j].x);
                    #pragma unroll
                    for (int r = 0; r < 4; ++r) fma2(acc[j][r], xp[r], c2);
                }
            }
        }
        __syncthreads();                      // release cur for prefetch ch+2
    }
    if (tid < 256) A_s[tid] = Aacc;
    __syncthreads();

    // ---- distances d = fl(fl(A + p) - 2g); per-thread first-min argmin ----
    float* rs   = xb0;                        // [NWARP][256] best distance
    int*   ri   = (int*)(xb0 + NWARP * 256);  // [NWARP][256] slice indices
    int*   best = (int*)(A_s);                // reuse A_s region? no: need A. use end:
    best = (int*)(xb0 + 2 * NWARP * 256);     // [256] (fits: 2*10*256+256 <= 8192)

    #pragma unroll
    for (int r = 0; r < 4; ++r) {
        // pixel pair for slot r: p0 = 4tx + 2*(r&1) + 128*(r>>1)
        const int p0 = (tx << 2) + ((r & 1) << 1) + ((r >> 1) << 7);
        const float2 Av = *(const float2*)&A_s[p0];
        float bd0 = F32_INF, bd1 = F32_INF;
        int   bi0 = 0,       bi1 = 0;
        #pragma unroll
        for (int j = 0; j < KPG; ++j) {
            const int kk = ty * KPG + j;
            const float p = p_s[kk];
            const float2 g = unpack2(acc[j][r]);
            const float d0 = __fadd_rn(__fadd_rn(Av.x, p), -(2.0f * g.x));
            const float d1 = __fadd_rn(__fadd_rn(Av.y, p), -(2.0f * g.y));
            if (d0 < bd0) { bd0 = d0; bi0 = kk; }  // strict < keeps lowest idx
            if (d1 < bd1) { bd1 = d1; bi1 = kk; }
        }
        rs[ty * 256 + p0]     = bd0;  ri[ty * 256 + p0]     = bi0;
        rs[ty * 256 + p0 + 1] = bd1;  ri[ty * 256 + p0 + 1] = bi1;
    }
    __syncthreads();

    if (tid < 256) {
        float bd = rs[tid];
        int   bi = ri[tid];
        #pragma unroll
        for (int t2 = 1; t2 < NWARP; ++t2) {
            const float s = rs[t2 * 256 + tid];
            if (s < bd) { bd = s; bi = ri[t2 * 256 + tid]; } // idx ascends w/ ty
        }
        best[tid] = bi;
    }
    __syncthreads();

    // ---- epilogue: z_q_x = fl(x + fl(codes - x)), z_q_x_bar = codes ----
    if (tid < 256) {
        const size_t obase = (size_t)b * D_DIM * HW_SZ + hw0;
        const float* zsrc  = z + obase;
        float* o0 = out + obase;
        float* o1 = out + (size_t)B_IMG * D_DIM * HW_SZ + obase;

        const int px0 = (tid & 63) << 2;
        const int d0  = tid >> 6;
        const float* c0 = cb_s + best[px0 + 0] * CBS2;
        const float* c1 = cb_s + best[px0 + 1] * CBS2;
        const float* c2 = cb_s + best[px0 + 2] * CBS2;
        const float* c3 = cb_s + best[px0 + 3] * CBS2;

        #pragma unroll 4
        for (int d = d0; d < D_DIM; d += 4) {
            const size_t off = (size_t)d * HW_SZ + px0;
            const float4 xv = *(const float4*)(zsrc + off);
            float4 cv;
            cv.x = c0[d]; cv.y = c1[d]; cv.z = c2[d]; cv.w = c3[d];
            float4 q;
            q.x = __fadd_rn(xv.x, __fadd_rn(cv.x, -xv.x));
            q.y = __fadd_rn(xv.y, __fadd_rn(cv.y, -xv.y));
            q.z = __fadd_rn(xv.z, __fadd_rn(cv.z, -xv.z));
            q.w = __fadd_rn(xv.w, __fadd_rn(cv.w, -xv.w));
            *(float4*)(o0 + off) = q;
            *(float4*)(o1 + off) = cv;
        }
    }
}

extern "C" void kernel_launch(void* const* d_in, const int* in_sizes, int n_in,
                              void* d_out, int out_size)
{
    const float* z      = (const float*)d_in[0];
    const float* cb     = (const float*)d_in[1];
    const int*   labels = (const int*)d_in[2];
    float*       out    = (float*)d_out;
    (void)in_sizes; (void)n_in; (void)out_size;

    // Class -> contiguous codebook range, replicating
    // round(linspace(-0.5, NCLS-0.51, K-NSHR)) exactly (double + half-even).
    ClassRanges cr;
    for (int c = 0; c < NCLS; ++c) { cr.lo[c] = 0; cr.cnt[c] = 0; }
    const double step = (((double)NCLS - 0.51) + 0.5) / (double)(K_CB - NSHR - 1);
    int prev = -1;
    for (int i = 0; i < K_CB - NSHR; ++i) {
        const double v = -0.5 + (double)i * step;
        int c = (int)nearbyint(v);
        if (c < 0) c = 0;
        if (c > NCLS - 1) c = NCLS - 1;
        if (c != prev) { cr.lo[c] = i; prev = c; }
        cr.cnt[c] += 1;
    }

    const size_t smem_bytes =
        (size_t)(KT * CBS2 + 64 + 256 + 2 * CHROWS * 256) * sizeof(float);
    cudaFuncSetAttribute(vq_kernel,
                         cudaFuncAttributeMaxDynamicSharedMemorySize,
                         (int)smem_bytes);

    dim3 grid(HW_SZ / TP, B_IMG);
    vq_kernel<<<grid, NTHR, smem_bytes>>>(z, cb, labels, out, cr);
}

// round 6
// speedup vs baseline: 1.0667x; 1.0667x over previous
#include <cuda_runtime.h>
#include <math.h>
#include <float.h>
#include <stdint.h>

// Problem constants (fixed by the reference)
#define B_IMG  32
#define D_DIM  256
#define HW_SZ  4096     // H*W = 64*64
#define K_CB   512
#define NCLS   10
#define NSHR   10

// Tiling
#define TP     256      // pixels per block
#define NTHR   256
#define NGRP   4        // code groups (tid>>6)
#define CPG    14       // usable codes per group (4*14 = 56 >= 51)
#define KTP    64       // cbT row stride: groups at 16-col boundaries (16B align)
#define CHROWS 32       // d-rows staged per chunk
#define NCHNK  (D_DIM / CHROWS)

#define F32_INF __int_as_float(0x7f800000)

struct ClassRanges { int lo[NCLS]; int cnt[NCLS]; };

typedef unsigned long long ull;

// ---- packed f32x2 helpers (Blackwell): exact per-lane IEEE fp32 semantics --
__device__ __forceinline__ ull pack2(float x) {
    unsigned int b = __float_as_uint(x);
    ull r;
    asm("mov.b64 %0, {%1, %1};" : "=l"(r) : "r"(b));
    return r;
}
__device__ __forceinline__ void fma2(ull& d, ull a, ull b) {
    asm("fma.rn.f32x2 %0, %1, %2, %0;" : "+l"(d) : "l"(a), "l"(b));
}
__device__ __forceinline__ float2 unpack2(ull v) {
    unsigned int lo, hi;
    asm("mov.b64 {%0, %1}, %2;" : "=r"(lo), "=r"(hi) : "l"(v));
    return make_float2(__uint_as_float(lo), __uint_as_float(hi));
}

// ----------------------------------------------------------------------------
// One block: image b, 256 contiguous pixels. Candidate codes = contiguous
// codebook slice [lo, lo+cnt), stored TRANSPOSED in smem: cbT[d][col],
// col = 16*(kk/14) + kk%14 (pad cols 14,15 of each 16-col group are zero).
//
// Bit-exact replication of the reference fp32 arithmetic (validated round 2):
//   A   = in_sqr  : sequential ascending sum of fl(x_d*x_d)  (mul then add)
//   g_k = x . c_k : sequential ascending fused-FMA chain
//   p_k = ||c_k||^2 (order non-critical vs ulp(256)=3e-5 decision grid)
//   d_k = fl( fl(A + p_k) - 2*g_k );  argmin, first-min tie-break
//   (storage col is monotone in code index, so col-ascending scan == k-ascending)
// ----------------------------------------------------------------------------
__global__ void __launch_bounds__(NTHR, 2)
vq_kernel(const float* __restrict__ z, const float* __restrict__ cb,
          const int* __restrict__ labels, float* __restrict__ out,
          ClassRanges cr)
{
    extern __shared__ float smem[];
    float* cbT_s = smem;                      // [256 d][KTP]
    float* p_s   = cbT_s + D_DIM * KTP;       // [KTP] cb_sqr by col (+inf pads)
    float* A_s   = p_s + KTP;                 // [256] in_sqr per pixel
    float* x_s   = A_s + 256;                 // [CHROWS][256], reused later

    const int tid = threadIdx.x;
    const int tx  = tid & 31;
    const int wid = tid >> 5;                 // warp 0..7
    const int t64 = tid & 63;                 // lane within code group
    const int ty2 = tid >> 6;                 // code group 0..3
    const int px0 = t64 << 2;                 // 4 owned pixels
    const int b   = blockIdx.y;
    const int hw0 = blockIdx.x * TP;

    const int label = labels[b];
    const int lo    = cr.lo[label];
    const int cnt   = cr.cnt[label];          // 50 or 51

    // ---- init p_s to +inf, zero cbT pad columns via full zero-fill ----
    if (tid < KTP) p_s[tid] = F32_INF;
    for (int i = tid; i < D_DIM * (KTP / 4); i += NTHR)
        *(float4*)&cbT_s[i << 2] = make_float4(0.f, 0.f, 0.f, 0.f);
    __syncthreads();

    // ---- build transposed codebook: cbT[d][col] = cb[lo+kk][d] ----
    for (int i = tid; i < 56 * (D_DIM / 4); i += NTHR) {
        const int kk  = i % 56;               // compact code index
        const int d4  = (i / 56) << 2;
        const int col = ((kk / CPG) << 4) + (kk % CPG);
        float4 v = make_float4(0.f, 0.f, 0.f, 0.f);
        if (kk < cnt) v = *(const float4*)(cb + (size_t)(lo + kk) * D_DIM + d4);
        cbT_s[(d4 + 0) * KTP + col] = v.x;
        cbT_s[(d4 + 1) * KTP + col] = v.y;
        cbT_s[(d4 + 2) * KTP + col] = v.z;
        cbT_s[(d4 + 3) * KTP + col] = v.w;
    }

    // ---- cb_sqr per code from GLOBAL cb (coalesced), warp w -> codes 7w.. ----
    #pragma unroll
    for (int j = 0; j < 7; ++j) {
        const int kk = wid * 7 + j;           // 0..55
        float s = 0.0f;
        if (kk < cnt) {
            const float* crow = cb + (size_t)(lo + kk) * D_DIM;
            #pragma unroll
            for (int d = tx; d < D_DIM; d += 32) {
                const float v = __ldg(crow + d);
                s = __fadd_rn(s, __fmul_rn(v, v));
            }
            #pragma unroll
            for (int o = 16; o > 0; o >>= 1)
                s = __fadd_rn(s, __shfl_xor_sync(0xffffffffu, s, o));
            if (tx == 0) {
                const int col = ((kk / CPG) << 4) + (kk % CPG);
                p_s[col] = s;
            }
        }
    }
    __syncthreads();

    // ---- main pass: 8 chunks of 32 d-rows ----
    // Thread owns 4 pixels (px0..px0+3) x 14 codes (cols 16*ty2 .. +13).
    // acc[j][p]: lanes = codes (col 16*ty2+2j, +2j+1) for pixel px0+p.
    ull acc[7][4];
    #pragma unroll
    for (int j = 0; j < 7; ++j)
        #pragma unroll
        for (int p = 0; p < 4; ++p) acc[j][p] = 0ULL;
    float Aacc = 0.0f;                        // in_sqr chain for pixel == tid

    const float* xbase = z + (size_t)b * D_DIM * HW_SZ + hw0;
    const int colbase = ty2 << 4;

    for (int ch = 0; ch < NCHNK; ++ch) {
        const int dc0 = ch * CHROWS;
        const float* xs = xbase + (size_t)dc0 * HW_SZ;
        __syncthreads();                      // protect x_s reuse
        // stage x chunk [32 d][256 px] (float4, coalesced; 8 per thread)
        for (int i = tid; i < CHROWS * 64; i += NTHR) {
            const int row = i >> 6;
            const int c4  = (i & 63) << 2;
            *(float4*)&x_s[(row << 8) + c4] =
                *(const float4*)(xs + (size_t)row * HW_SZ + c4);
        }
        __syncthreads();

        // in_sqr: thread owns pixel tid, ascending d (bit-exact order)
        #pragma unroll
        for (int dd = 0; dd < CHROWS; ++dd) {
            const float v = x_s[(dd << 8) + tid];
            Aacc = __fadd_rn(Aacc, __fmul_rn(v, v));
        }

        // GEMM: per d, codes arrive as float4 broadcasts (pairs over k)
        #pragma unroll 4
        for (int dd = 0; dd < CHROWS; ++dd) {
            const float* crow = cbT_s + (size_t)(dc0 + dd) * KTP + colbase;
            const float4 ca = *(const float4*)(crow + 0);
            const float4 cbv = *(const float4*)(crow + 4);
            const float4 cc = *(const float4*)(crow + 8);
            const float2 cd = *(const float2*)(crow + 12);
            ull c[7];
            c[0] = *(const ull*)&ca.x;  c[1] = *(const ull*)&ca.z;
            c[2] = *(const ull*)&cbv.x; c[3] = *(const ull*)&cbv.z;
            c[4] = *(const ull*)&cc.x;  c[5] = *(const ull*)&cc.z;
            c[6] = *(const ull*)&cd.x;

            const float4 xv = *(const float4*)&x_s[(dd << 8) + px0];
            ull xd[4];
            xd[0] = pack2(xv.x); xd[1] = pack2(xv.y);
            xd[2] = pack2(xv.z); xd[3] = pack2(xv.w);

            #pragma unroll
            for (int j = 0; j < 7; ++j)
                #pragma unroll
                for (int p = 0; p < 4; ++p) fma2(acc[j][p], xd[p], c[j]);
        }
    }
    A_s[tid] = Aacc;
    __syncthreads();

    // ---- distances d = fl(fl(A + p) - 2g); per-thread first-min argmin ----
    float* rs   = x_s;                        // [NGRP][256] best distance
    int*   ri   = (int*)(x_s + NGRP * 256);   // [NGRP][256] storage cols
    int*   best = (int*)(x_s + 2 * NGRP * 256); // [256]

    #pragma unroll
    for (int p = 0; p < 4; ++p) {
        const float Av = A_s[px0 + p];
        float bd = F32_INF;
        int   bi = colbase;
        #pragma unroll
        for (int j = 0; j < 7; ++j) {
            const int c0i = colbase + (j << 1);
            const float2 g = unpack2(acc[j][p]);
            const float d0 = __fadd_rn(__fadd_rn(Av, p_s[c0i]), -(2.0f * g.x));
            const float d1 = __fadd_rn(__fadd_rn(Av, p_s[c0i + 1]), -(2.0f * g.y));
            if (d0 < bd) { bd = d0; bi = c0i; }      // strict <: lowest col wins
            if (d1 < bd) { bd = d1; bi = c0i + 1; }
        }
        rs[ty2 * 256 + px0 + p] = bd;
        ri[ty2 * 256 + px0 + p] = bi;
    }
    __syncthreads();

    {
        float bd = rs[tid];
        int   bi = ri[tid];
        #pragma unroll
        for (int t2 = 1; t2 < NGRP; ++t2) {
            const float s = rs[t2 * 256 + tid];
            if (s < bd) { bd = s; bi = ri[t2 * 256 + tid]; } // col ascends w/ grp
        }
        best[tid] = bi;
    }
    __syncthreads();

    // ---- epilogue: z_q_x = fl(x + fl(codes - x)), z_q_x_bar = codes ----
    const size_t obase = (size_t)b * D_DIM * HW_SZ + hw0;
    const float* zsrc  = z + obase;
    float* o0 = out + obase;
    float* o1 = out + (size_t)B_IMG * D_DIM * HW_SZ + obase;

    const int ep0 = (tid & 63) << 2;          // 4 pixels
    const int ed0 = tid >> 6;                 // d phase
    const int b0 = best[ep0 + 0];
    const int b1 = best[ep0 + 1];
    const int b2 = best[ep0 + 2];
    const int b3 = best[ep0 + 3];

    #pragma unroll 4
    for (int d = ed0; d < D_DIM; d += 4) {
        const size_t off = (size_t)d * HW_SZ + ep0;
        const float* crow = cbT_s + (size_t)d * KTP;
        const float4 xv = *(const float4*)(zsrc + off);
        float4 cv;
        cv.x = crow[b0]; cv.y = crow[b1]; cv.z = crow[b2]; cv.w = crow[b3];
        float4 q;
        q.x = __fadd_rn(xv.x, __fadd_rn(cv.x, -xv.x));
        q.y = __fadd_rn(xv.y, __fadd_rn(cv.y, -xv.y));
        q.z = __fadd_rn(xv.z, __fadd_rn(cv.z, -xv.z));
        q.w = __fadd_rn(xv.w, __fadd_rn(cv.w, -xv.w));
        *(float4*)(o0 + off) = q;
        *(float4*)(o1 + off) = cv;
    }
}

extern "C" void kernel_launch(void* const* d_in, const int* in_sizes, int n_in,
                              void* d_out, int out_size)
{
    const float* z      = (const float*)d_in[0];
    const float* cb     = (const float*)d_in[1];
    const int*   labels = (const int*)d_in[2];
    float*       out    = (float*)d_out;
    (void)in_sizes; (void)n_in; (void)out_size;

    // Class -> contiguous codebook range, replicating
    // round(linspace(-0.5, NCLS-0.51, K-NSHR)) exactly (double + half-even).
    ClassRanges cr;
    for (int c = 0; c < NCLS; ++c) { cr.lo[c] = 0; cr.cnt[c] = 0; }
    const double step = (((double)NCLS - 0.51) + 0.5) / (double)(K_CB - NSHR - 1);
    int prev = -1;
    for (int i = 0; i < K_CB - NSHR; ++i) {
        const double v = -0.5 + (double)i * step;
        int c = (int)nearbyint(v);
        if (c < 0) c = 0;
        if (c > NCLS - 1) c = NCLS - 1;
        if (c != prev) { cr.lo[c] = i; prev = c; }
        cr.cnt[c] += 1;
    }

    const size_t smem_bytes =
        (size_t)(D_DIM * KTP + KTP + 256 + CHROWS * 256) * sizeof(float);
    cudaFuncSetAttribute(vq_kernel,
                         cudaFuncAttributeMaxDynamicSharedMemorySize,
                         (int)smem_bytes);

    dim3 grid(HW_SZ / TP, B_IMG);
    vq_kernel<<<grid, NTHR, smem_bytes>>>(z, cb, labels, out, cr);
}